// round 11
// baseline (speedup 1.0000x reference)
#include <cuda_runtime.h>
#include <math.h>

#define NB 4
#define TDIM 8
#define LP1 197
#define HH 12
#define DD 64
#define CC 768
#define LL 196
#define NT 28   // NB*(TDIM-1)

typedef unsigned long long u64;

__device__ __forceinline__ u64 pk2(float lo, float hi) {
    u64 r; asm("mov.b64 %0,{%1,%2};" : "=l"(r) : "f"(lo), "f"(hi)); return r;
}
__device__ __forceinline__ void upk2(u64 v, float& lo, float& hi) {
    asm("mov.b64 {%0,%1},%2;" : "=f"(lo), "=f"(hi) : "l"(v));
}
__device__ __forceinline__ u64 ffma2(u64 a, u64 b, u64 c) {
    u64 d; asm("fma.rn.f32x2 %0,%1,%2,%3;" : "=l"(d) : "l"(a), "l"(b), "l"(c)); return d;
}
__device__ __forceinline__ u64 fadd2(u64 a, u64 b) {
    u64 d; asm("add.rn.f32x2 %0,%1,%2;" : "=l"(d) : "l"(a), "l"(b)); return d;
}
__device__ __forceinline__ void red4(float* p, float a, float b, float c, float d) {
    asm volatile("red.global.add.v4.f32 [%0], {%1,%2,%3,%4};"
                 :: "l"(p), "f"(a), "f"(b), "f"(c), "f"(d) : "memory");
}

// Scratch: head-averaged attention probabilities for each half.
__device__ float g_P1[NT * LL * LL];
__device__ float g_P2[NT * LL * LL];

// ---------------------------------------------------------------------------
// Kernel 0: zero P scratch and the cls (q=0) rows of out.
// ---------------------------------------------------------------------------
__global__ void zero_kernel(float* __restrict__ out) {
    size_t stride = (size_t)gridDim.x * blockDim.x;
    size_t i = (size_t)blockIdx.x * blockDim.x + threadIdx.x;
    const size_t np = (size_t)NT * LL * LL;
    for (size_t j = i; j < np; j += stride) { g_P1[j] = 0.f; g_P2[j] = 0.f; }
    const size_t ncls = (size_t)NB * TDIM * CC;
    for (size_t j = i; j < ncls; j += stride) {
        size_t nt = j / CC, c = j - nt * CC;
        out[(nt * LP1) * CC + c] = 0.f;
    }
}

// ---------------------------------------------------------------------------
// Kernel 1: attention, tk-keyed K-tile SHARING.
// Block = (h, n*8+tk, qh).  Stage K(n,tk,h) ONCE, then:
//   pass A (tk<=6): Q(n,tk+1) rows -> softmax -> P1[n*7+tk]
//   pass B (tk>=1): Q(n,tk-1) rows -> softmax -> P2[n*7+tk-1]
// K staging lanes/tile halved vs R10 (2016 -> 1152 stages); GEMM/softmax/REDG
// per unit work identical to R10.  256 threads (16x16), 3 CTAs/SM.
// ---------------------------------------------------------------------------
#define KS_STRIDE 210
#define QS_STRIDE 69
#define A_SMEM_BYTES ((64*KS_STRIDE + 64*QS_STRIDE) * 4)   // 71424 B

// Scaled-probability store: pv[b] holds cols (32b+2tx, 32b+2tx+1) of this row.
// Even tx gathers odd neighbor's pair -> one 16B quad -> red4 (half REDG lanes).
__device__ __forceinline__ void store_row_v4(float* Pr, const u64* pv, int tx) {
    #pragma unroll
    for (int b = 0; b < 7; b++) {
        u64 nb = __shfl_down_sync(0xffffffffu, pv[b], 1);
        if ((tx & 1) == 0 && (b < 6 || tx == 0)) {
            float a0, a1, b0, b1;
            upk2(pv[b], a0, a1);
            upk2(nb,    b0, b1);
            red4(Pr + 32 * b + 2 * tx, a0, a1, b0, b1);
        }
    }
}

// One half-pass over the resident K tile: stage Q rows, GEMM, softmax, REDG.
// Contains __syncthreads — must be called uniformly by the whole block.
__device__ __forceinline__ void attn_pass(
    const float* __restrict__ qb, float* __restrict__ P,
    const float* __restrict__ ks, float* __restrict__ qs,
    int tid, int tx, int ty, int q0, int nrows, int qh)
{
    __syncthreads();   // prior pass's qs reads (and K-stage STS on pass A) done
    for (int i = tid; i < nrows * DD; i += 256) {
        int qq = i >> 6, d = i & 63;
        qs[d * QS_STRIDE + qq] = qb[(size_t)(q0 + qq) * (HH * DD) + d] * 0.125f;
    }
    __syncthreads();

    // Main 64x196 GEMM over K=64: 4 rows x 7 col-pairs per thread, all valid.
    u64 acc[4][7];
    #pragma unroll
    for (int a = 0; a < 4; a++)
        #pragma unroll
        for (int b = 0; b < 7; b++) acc[a][b] = 0ULL;

    #pragma unroll 4
    for (int d = 0; d < 64; d++) {
        u64 ad[4], bv[7];
        #pragma unroll
        for (int a = 0; a < 4; a++) {
            float av = qs[d * QS_STRIDE + ty + 16 * a];
            ad[a] = pk2(av, av);
        }
        #pragma unroll
        for (int b = 0; b < 7; b++)
            bv[b] = *(const u64*)&ks[d * KS_STRIDE + 2 * tx + 32 * b];
        #pragma unroll
        for (int a = 0; a < 4; a++)
            #pragma unroll
            for (int b = 0; b < 7; b++)
                acc[a][b] = ffma2(ad[a], bv[b], acc[a][b]);
    }

    // Register softmax per row (half-warp owns a row); no row guards.
    #pragma unroll
    for (int a = 0; a < 4; a++) {
        float e[14];
        #pragma unroll
        for (int b = 0; b < 7; b++) upk2(acc[a][b], e[2 * b], e[2 * b + 1]);

        bool v6 = (tx < 2);
        float mx = -1e30f;
        #pragma unroll
        for (int b = 0; b < 6; b++) mx = fmaxf(mx, fmaxf(e[2 * b], e[2 * b + 1]));
        if (v6) mx = fmaxf(mx, fmaxf(e[12], e[13]));
        #pragma unroll
        for (int off = 8; off > 0; off >>= 1)
            mx = fmaxf(mx, __shfl_xor_sync(0xffffffffu, mx, off));

        float s = 0.f;
        #pragma unroll
        for (int b = 0; b < 6; b++) {
            e[2 * b]     = __expf(e[2 * b] - mx);
            e[2 * b + 1] = __expf(e[2 * b + 1] - mx);
            s += e[2 * b] + e[2 * b + 1];
        }
        if (v6) {
            e[12] = __expf(e[12] - mx);
            e[13] = __expf(e[13] - mx);
            s += e[12] + e[13];
        }
        #pragma unroll
        for (int off = 8; off > 0; off >>= 1)
            s += __shfl_xor_sync(0xffffffffu, s, off);

        float inv = (1.f / 12.f) / s;
        u64 pv[7];
        #pragma unroll
        for (int b = 0; b < 7; b++)
            pv[b] = pk2(e[2 * b] * inv, e[2 * b + 1] * inv);
        store_row_v4(P + (size_t)(q0 + ty + 16 * a) * LL, pv, tx);
    }

    // Global 4-row tail (rows 192..195), qh==2 blocks only.
    if (qh == 2) {
        int qq2 = 64 + (ty & 3);
        u64 acct[7];
        #pragma unroll
        for (int b = 0; b < 7; b++) acct[b] = 0ULL;

        #pragma unroll 4
        for (int d = 0; d < 64; d++) {
            float av = qs[d * QS_STRIDE + qq2];
            u64 ad = pk2(av, av);
            #pragma unroll
            for (int b = 0; b < 7; b++)
                acct[b] = ffma2(ad, *(const u64*)&ks[d * KS_STRIDE + 2 * tx + 32 * b], acct[b]);
        }

        float e[14];
        #pragma unroll
        for (int b = 0; b < 7; b++) upk2(acct[b], e[2 * b], e[2 * b + 1]);

        bool v6 = (tx < 2);
        float mx = -1e30f;
        #pragma unroll
        for (int b = 0; b < 6; b++) mx = fmaxf(mx, fmaxf(e[2 * b], e[2 * b + 1]));
        if (v6) mx = fmaxf(mx, fmaxf(e[12], e[13]));
        #pragma unroll
        for (int off = 8; off > 0; off >>= 1)
            mx = fmaxf(mx, __shfl_xor_sync(0xffffffffu, mx, off));

        float s = 0.f;
        #pragma unroll
        for (int b = 0; b < 6; b++) {
            e[2 * b]     = __expf(e[2 * b] - mx);
            e[2 * b + 1] = __expf(e[2 * b + 1] - mx);
            s += e[2 * b] + e[2 * b + 1];
        }
        if (v6) {
            e[12] = __expf(e[12] - mx);
            e[13] = __expf(e[13] - mx);
            s += e[12] + e[13];
        }
        #pragma unroll
        for (int off = 8; off > 0; off >>= 1)
            s += __shfl_xor_sync(0xffffffffu, s, off);

        float inv = (1.f / 12.f) / s;
        u64 pv[7];
        #pragma unroll
        for (int b = 0; b < 7; b++)
            pv[b] = pk2(e[2 * b] * inv, e[2 * b + 1] * inv);
        #pragma unroll
        for (int b = 0; b < 7; b++) {
            u64 nb = __shfl_down_sync(0xffffffffu, pv[b], 1);
            if (ty < 4 && (tx & 1) == 0 && (b < 6 || tx == 0)) {
                float a0, a1, b0, b1;
                upk2(pv[b], a0, a1);
                upk2(nb,    b0, b1);
                red4(P + (size_t)(192 + ty) * LL + 32 * b + 2 * tx, a0, a1, b0, b1);
            }
        }
    }
}

__global__ __launch_bounds__(256, 3)
void attn_kernel(const float* __restrict__ q, const float* __restrict__ k) {
    extern __shared__ float sm[];
    float* ks = sm;                          // [64][210]
    float* qs = ks + 64 * KS_STRIDE;         // [64][69]  (up to 68 rows used)

    int h  = blockIdx.x;
    int y  = blockIdx.y;
    int n  = y >> 3, tk = y & 7;
    int qh = blockIdx.z;
    int q0 = qh * 64;
    int nrows = (qh == 2) ? 68 : 64;

    const float* kb = k + ((size_t)(n * TDIM + tk) * LP1 + 1) * (HH * DD) + h * DD;
    int tid = threadIdx.x;
    int tx = tid & 15, ty = tid >> 4;

    // Stage K tile ONCE, transposed: ks[d][kk] = k[kk][d]
    for (int i = tid; i < LL * DD; i += 256) {
        int kk = i >> 6, d = i & 63;
        ks[d * KS_STRIDE + kk] = kb[(size_t)kk * (HH * DD) + d];
    }

    // Pass A (half 0): q time tk+1, output P1[n*7+tk]
    if (tk <= 6) {
        const float* qb = q + ((size_t)(n * TDIM + tk + 1) * LP1 + 1) * (HH * DD) + h * DD;
        float* P = g_P1 + (size_t)(n * 7 + tk) * LL * LL;
        attn_pass(qb, P, ks, qs, tid, tx, ty, q0, nrows, qh);
    }

    // Pass B (half 1): q time tk-1, output P2[n*7+tk-1]
    if (tk >= 1) {
        const float* qb = q + ((size_t)(n * TDIM + tk - 1) * LP1 + 1) * (HH * DD) + h * DD;
        float* P = g_P2 + (size_t)(n * 7 + tk - 1) * LL * LL;
        attn_pass(qb, P, ks, qs, tid, tx, ty, q0, nrows, qh);
    }
}

// ---------------------------------------------------------------------------
// Kernel 2 (fused halves, np-merged) — EXACT ROUND-8 VERSION (protected win).
// ---------------------------------------------------------------------------
#define TCo 64
#define WS_FLOATS (98 * TCo)            // 6272
#define PS_FLOATS (4 * LL * 8)          // 6272 per half (4 n)
#define O_SMEM_BYTES ((WS_FLOATS + 2 * PS_FLOATS) * 4)   // 75264 B

__global__ __launch_bounds__(256, 3)
void out_kernel(const float* __restrict__ w1, const float* __restrict__ w2,
                float* __restrict__ out) {
    extern __shared__ float sm[];
    float* ws  = sm;                    // [98][64]
    float* psA = sm + WS_FLOATS;        // [4][196*8]  slot tt = P1[t=tt-1], slot0=0
    float* psB = psA + PS_FLOATS;       // [4][196*8]  slot tt = P2[tt],    slot7=0

    int qq = blockIdx.y;
    int c0 = blockIdx.x * TCo;
    int tid = threadIdx.x;
    int pi = qq / 14, pj = qq - pi * 14;

    #pragma unroll
    for (int r = 0; r < 28; r++) {
        int n_l = r / 7, t = r - n_l * 7;
        if (tid < LL) {
            size_t base = ((size_t)(n_l * 7 + t) * LL + qq) * LL + tid;
            psA[n_l * (LL * 8) + tid * 8 + t + 1] = g_P1[base];
            psB[n_l * (LL * 8) + tid * 8 + t]     = g_P2[base];
        }
    }
    if (tid < LL) {
        #pragma unroll
        for (int n_l = 0; n_l < 4; n_l++) {
            psA[n_l * (LL * 8) + tid * 8] = 0.f;
            psB[n_l * (LL * 8) + tid * 8 + 7] = 0.f;
        }
    }

    int wid = tid >> 5, lane = tid & 31;
    int n_l = wid >> 1, kq = wid & 1;
    int sub = lane >> 4, cl = lane & 15;
    int kst = kq * 49;

    u64 acc[8];
    #pragma unroll
    for (int i = 0; i < 8; i++) acc[i] = 0ULL;

    #pragma unroll
    for (int ph = 0; ph < 4; ph++) {
        const float* w = (ph < 2) ? w1 : w2;
        const float* ps = ((ph < 2) ? psA : psB) + n_l * (LL * 8);
        int kbase = (ph & 1) * 98;

        __syncthreads();
        for (int i = tid; i < 98 * 16; i += 256) {
            int kk = i >> 4, cq = i & 15;
            int kg = kbase + kk;
            int ki = kg / 14, kj = kg - ki * 14;
            int idx = (pi - ki + 13) * 27 + (pj - kj + 13);
            *(float4*)&ws[kk * TCo + cq * 4] =
                *(const float4*)(w + (size_t)idx * CC + c0 + cq * 4);
        }
        __syncthreads();

        #pragma unroll 7
        for (int kl = kst; kl < kst + 49; kl++) {
            float4 wv = *(const float4*)&ws[kl * TCo + cl * 4];
            ulonglong2 pp = *(const ulonglong2*)&ps[(kbase + kl) * 8 + sub * 4];
            u64 b0 = pk2(wv.x, wv.x), b1 = pk2(wv.y, wv.y);
            u64 b2 = pk2(wv.z, wv.z), b3 = pk2(wv.w, wv.w);
            acc[0] = ffma2(pp.x, b0, acc[0]);  acc[1] = ffma2(pp.y, b0, acc[1]);
            acc[2] = ffma2(pp.x, b1, acc[2]);  acc[3] = ffma2(pp.y, b1, acc[3]);
            acc[4] = ffma2(pp.x, b2, acc[4]);  acc[5] = ffma2(pp.y, b2, acc[5]);
            acc[6] = ffma2(pp.x, b3, acc[6]);  acc[7] = ffma2(pp.y, b3, acc[7]);
        }
    }

    __syncthreads();
    u64* red = (u64*)ws;
    if (kq) {
        int base = (n_l * 32 + lane) * 8;
        #pragma unroll
        for (int j = 0; j < 8; j++) red[base + j] = acc[j];
    }
    __syncthreads();

    if (kq == 0) {
        int base = (n_l * 32 + lane) * 8;
        #pragma unroll
        for (int j = 0; j < 8; j++) acc[j] = fadd2(acc[j], red[base + j]);

        float a[16];
        #pragma unroll
        for (int i = 0; i < 8; i++) upk2(acc[i], a[2 * i], a[2 * i + 1]);
        #pragma unroll
        for (int tl = 0; tl < 4; tl++) {
            int tt = sub * 4 + tl;
            int tp = tl >> 1, hi = tl & 1;
            float4 o4;
            o4.x = a[(0 * 2 + tp) * 2 + hi];
            o4.y = a[(1 * 2 + tp) * 2 + hi];
            o4.z = a[(2 * 2 + tp) * 2 + hi];
            o4.w = a[(3 * 2 + tp) * 2 + hi];
            *(float4*)(out + ((size_t)(n_l * TDIM + tt) * LP1 + qq + 1) * CC
                       + c0 + cl * 4) = o4;
        }
    }
}

// ---------------------------------------------------------------------------
extern "C" void kernel_launch(void* const* d_in, const int* in_sizes, int n_in,
                              void* d_out, int out_size) {
    const float* q  = (const float*)d_in[0];
    const float* k  = (const float*)d_in[1];
    const float* w1 = (const float*)d_in[2];
    const float* w2 = (const float*)d_in[3];
    float* out = (float*)d_out;

    cudaFuncSetAttribute(attn_kernel, cudaFuncAttributeMaxDynamicSharedMemorySize, A_SMEM_BYTES);
    cudaFuncSetAttribute(out_kernel,  cudaFuncAttributeMaxDynamicSharedMemorySize, O_SMEM_BYTES);

    zero_kernel<<<512, 256>>>(out);
    attn_kernel<<<dim3(HH, NB * TDIM, 3), 256, A_SMEM_BYTES>>>(q, k);
    out_kernel<<<dim3(CC / TCo, LL, 1), 256, O_SMEM_BYTES>>>(w1, w2, out);
}

// round 12
// speedup vs baseline: 1.2045x; 1.2045x over previous
#include <cuda_runtime.h>
#include <math.h>

#define NB 4
#define TDIM 8
#define LP1 197
#define HH 12
#define DD 64
#define CC 768
#define LL 196
#define NT 28   // NB*(TDIM-1)

typedef unsigned long long u64;

__device__ __forceinline__ u64 pk2(float lo, float hi) {
    u64 r; asm("mov.b64 %0,{%1,%2};" : "=l"(r) : "f"(lo), "f"(hi)); return r;
}
__device__ __forceinline__ void upk2(u64 v, float& lo, float& hi) {
    asm("mov.b64 {%0,%1},%2;" : "=f"(lo), "=f"(hi) : "l"(v));
}
__device__ __forceinline__ u64 ffma2(u64 a, u64 b, u64 c) {
    u64 d; asm("fma.rn.f32x2 %0,%1,%2,%3;" : "=l"(d) : "l"(a), "l"(b), "l"(c)); return d;
}
__device__ __forceinline__ u64 fadd2(u64 a, u64 b) {
    u64 d; asm("add.rn.f32x2 %0,%1,%2;" : "=l"(d) : "l"(a), "l"(b)); return d;
}
__device__ __forceinline__ void red4(float* p, float a, float b, float c, float d) {
    asm volatile("red.global.add.v4.f32 [%0], {%1,%2,%3,%4};"
                 :: "l"(p), "f"(a), "f"(b), "f"(c), "f"(d) : "memory");
}

// Scratch: head-averaged attention probabilities for each half.
__device__ float g_P1[NT * LL * LL];
__device__ float g_P2[NT * LL * LL];

// ---------------------------------------------------------------------------
// Kernel 0: zero P scratch and the cls (q=0) rows of out.
// ---------------------------------------------------------------------------
__global__ void zero_kernel(float* __restrict__ out) {
    size_t stride = (size_t)gridDim.x * blockDim.x;
    size_t i = (size_t)blockIdx.x * blockDim.x + threadIdx.x;
    const size_t np = (size_t)NT * LL * LL;
    for (size_t j = i; j < np; j += stride) { g_P1[j] = 0.f; g_P2[j] = 0.f; }
    const size_t ncls = (size_t)NB * TDIM * CC;
    for (size_t j = i; j < ncls; j += stride) {
        size_t nt = j / CC, c = j - nt * CC;
        out[(nt * LP1) * CC + c] = 0.f;
    }
}

// ---------------------------------------------------------------------------
// Kernel 1: attention — EXACT ROUND-10 VERSION (protected best: z=3 chunking,
// register softmax, v4 paired REDG).  R11's K-tile sharing regressed on wave
// quantization; uniform short blocks win at this grid size.
// ---------------------------------------------------------------------------
#define KS_STRIDE 210
#define QS_STRIDE 69
#define A_SMEM_BYTES ((64*KS_STRIDE + 64*QS_STRIDE) * 4)   // 71424 B

__device__ __forceinline__ void store_row_v4(float* Pr, const u64* pv, int tx) {
    #pragma unroll
    for (int b = 0; b < 7; b++) {
        u64 nb = __shfl_down_sync(0xffffffffu, pv[b], 1);
        if ((tx & 1) == 0 && (b < 6 || tx == 0)) {
            float a0, a1, b0, b1;
            upk2(pv[b], a0, a1);
            upk2(nb,    b0, b1);
            red4(Pr + 32 * b + 2 * tx, a0, a1, b0, b1);
        }
    }
}

__global__ __launch_bounds__(256, 3)
void attn_kernel(const float* __restrict__ q, const float* __restrict__ k) {
    extern __shared__ float sm[];
    float* ks = sm;                          // [64][210]
    float* qs = ks + 64 * KS_STRIDE;         // [64][69]  (up to 68 rows used)

    int h    = blockIdx.x;
    int nt   = blockIdx.y;
    int half = blockIdx.z / 3;
    int qh   = blockIdx.z - half * 3;
    int n = nt / 7, t = nt - n * 7;
    int tq = (half == 0) ? t + 1 : t;
    int tk = (half == 0) ? t : t + 1;
    int q0 = qh * 64;
    int nrows = (qh == 2) ? 68 : 64;

    const float* qb = q + ((size_t)(n * TDIM + tq) * LP1 + 1) * (HH * DD) + h * DD;
    const float* kb = k + ((size_t)(n * TDIM + tk) * LP1 + 1) * (HH * DD) + h * DD;
    float* P = ((half == 0) ? g_P1 : g_P2) + (size_t)nt * LL * LL;

    int tid = threadIdx.x;

    for (int i = tid; i < LL * DD; i += 256) {
        int kk = i >> 6, d = i & 63;
        ks[d * KS_STRIDE + kk] = kb[(size_t)kk * (HH * DD) + d];
    }
    for (int i = tid; i < nrows * DD; i += 256) {
        int qq = i >> 6, d = i & 63;
        qs[d * QS_STRIDE + qq] = qb[(size_t)(q0 + qq) * (HH * DD) + d] * 0.125f;
    }
    __syncthreads();

    int tx = tid & 15, ty = tid >> 4;

    u64 acc[4][7];
    #pragma unroll
    for (int a = 0; a < 4; a++)
        #pragma unroll
        for (int b = 0; b < 7; b++) acc[a][b] = 0ULL;

    #pragma unroll 4
    for (int d = 0; d < 64; d++) {
        u64 ad[4], bv[7];
        #pragma unroll
        for (int a = 0; a < 4; a++) {
            float av = qs[d * QS_STRIDE + ty + 16 * a];
            ad[a] = pk2(av, av);
        }
        #pragma unroll
        for (int b = 0; b < 7; b++)
            bv[b] = *(const u64*)&ks[d * KS_STRIDE + 2 * tx + 32 * b];
        #pragma unroll
        for (int a = 0; a < 4; a++)
            #pragma unroll
            for (int b = 0; b < 7; b++)
                acc[a][b] = ffma2(ad[a], bv[b], acc[a][b]);
    }

    #pragma unroll
    for (int a = 0; a < 4; a++) {
        float e[14];
        #pragma unroll
        for (int b = 0; b < 7; b++) upk2(acc[a][b], e[2 * b], e[2 * b + 1]);

        bool v6 = (tx < 2);
        float mx = -1e30f;
        #pragma unroll
        for (int b = 0; b < 6; b++) mx = fmaxf(mx, fmaxf(e[2 * b], e[2 * b + 1]));
        if (v6) mx = fmaxf(mx, fmaxf(e[12], e[13]));
        #pragma unroll
        for (int off = 8; off > 0; off >>= 1)
            mx = fmaxf(mx, __shfl_xor_sync(0xffffffffu, mx, off));

        float s = 0.f;
        #pragma unroll
        for (int b = 0; b < 6; b++) {
            e[2 * b]     = __expf(e[2 * b] - mx);
            e[2 * b + 1] = __expf(e[2 * b + 1] - mx);
            s += e[2 * b] + e[2 * b + 1];
        }
        if (v6) {
            e[12] = __expf(e[12] - mx);
            e[13] = __expf(e[13] - mx);
            s += e[12] + e[13];
        }
        #pragma unroll
        for (int off = 8; off > 0; off >>= 1)
            s += __shfl_xor_sync(0xffffffffu, s, off);

        float inv = (1.f / 12.f) / s;
        u64 pv[7];
        #pragma unroll
        for (int b = 0; b < 7; b++)
            pv[b] = pk2(e[2 * b] * inv, e[2 * b + 1] * inv);
        store_row_v4(P + (size_t)(q0 + ty + 16 * a) * LL, pv, tx);
    }

    if (qh == 2) {
        int qq2 = 64 + (ty & 3);
        u64 acct[7];
        #pragma unroll
        for (int b = 0; b < 7; b++) acct[b] = 0ULL;

        #pragma unroll 4
        for (int d = 0; d < 64; d++) {
            float av = qs[d * QS_STRIDE + qq2];
            u64 ad = pk2(av, av);
            #pragma unroll
            for (int b = 0; b < 7; b++)
                acct[b] = ffma2(ad, *(const u64*)&ks[d * KS_STRIDE + 2 * tx + 32 * b], acct[b]);
        }

        float e[14];
        #pragma unroll
        for (int b = 0; b < 7; b++) upk2(acct[b], e[2 * b], e[2 * b + 1]);

        bool v6 = (tx < 2);
        float mx = -1e30f;
        #pragma unroll
        for (int b = 0; b < 6; b++) mx = fmaxf(mx, fmaxf(e[2 * b], e[2 * b + 1]));
        if (v6) mx = fmaxf(mx, fmaxf(e[12], e[13]));
        #pragma unroll
        for (int off = 8; off > 0; off >>= 1)
            mx = fmaxf(mx, __shfl_xor_sync(0xffffffffu, mx, off));

        float s = 0.f;
        #pragma unroll
        for (int b = 0; b < 6; b++) {
            e[2 * b]     = __expf(e[2 * b] - mx);
            e[2 * b + 1] = __expf(e[2 * b + 1] - mx);
            s += e[2 * b] + e[2 * b + 1];
        }
        if (v6) {
            e[12] = __expf(e[12] - mx);
            e[13] = __expf(e[13] - mx);
            s += e[12] + e[13];
        }
        #pragma unroll
        for (int off = 8; off > 0; off >>= 1)
            s += __shfl_xor_sync(0xffffffffu, s, off);

        float inv = (1.f / 12.f) / s;
        u64 pv[7];
        #pragma unroll
        for (int b = 0; b < 7; b++)
            pv[b] = pk2(e[2 * b] * inv, e[2 * b + 1] * inv);
        #pragma unroll
        for (int b = 0; b < 7; b++) {
            u64 nb = __shfl_down_sync(0xffffffffu, pv[b], 1);
            if (ty < 4 && (tx & 1) == 0 && (b < 6 || tx == 0)) {
                float a0, a1, b0, b1;
                upk2(pv[b], a0, a1);
                upk2(nb,    b0, b1);
                red4(P + (size_t)(192 + ty) * LL + 32 * b + 2 * tx, a0, a1, b0, b1);
            }
        }
    }
}

// ---------------------------------------------------------------------------
// Kernel 2 (fused halves, np-merged + c-tile-PAIRED): block = (c-pair of 128, q).
// P staged ONCE per block, reused across two 64-col sub-tiles -> P re-stage
// traffic and block prologues halved vs R8 (2352 -> 1176 blocks).
// acc (8 u64) written out and reset between sub-tiles: registers and smem
// byte-identical to the protected R8 inner loop.
// ---------------------------------------------------------------------------
#define TCo 64
#define WS_FLOATS (98 * TCo)            // 6272
#define PS_FLOATS (4 * LL * 8)          // 6272 per half (4 n)
#define O_SMEM_BYTES ((WS_FLOATS + 2 * PS_FLOATS) * 4)   // 75264 B

__global__ __launch_bounds__(256, 3)
void out_kernel(const float* __restrict__ w1, const float* __restrict__ w2,
                float* __restrict__ out) {
    extern __shared__ float sm[];
    float* ws  = sm;                    // [98][64]
    float* psA = sm + WS_FLOATS;        // [4][196*8]  slot tt = P1[t=tt-1], slot0=0
    float* psB = psA + PS_FLOATS;       // [4][196*8]  slot tt = P2[tt],    slot7=0

    int qq = blockIdx.y;
    int c0 = blockIdx.x * (2 * TCo);
    int tid = threadIdx.x;
    int pi = qq / 14, pj = qq - pi * 14;

    // Stage P rows t-strided for all 4 n, both halves (ONCE per block).
    #pragma unroll
    for (int r = 0; r < 28; r++) {
        int n_l = r / 7, t = r - n_l * 7;
        if (tid < LL) {
            size_t base = ((size_t)(n_l * 7 + t) * LL + qq) * LL + tid;
            psA[n_l * (LL * 8) + tid * 8 + t + 1] = g_P1[base];
            psB[n_l * (LL * 8) + tid * 8 + t]     = g_P2[base];
        }
    }
    if (tid < LL) {
        #pragma unroll
        for (int n_l = 0; n_l < 4; n_l++) {
            psA[n_l * (LL * 8) + tid * 8] = 0.f;
            psB[n_l * (LL * 8) + tid * 8 + 7] = 0.f;
        }
    }

    int wid = tid >> 5, lane = tid & 31;
    int n_l = wid >> 1, kq = wid & 1;
    int sub = lane >> 4, cl = lane & 15;
    int kst = kq * 49;

    #pragma unroll
    for (int ch = 0; ch < 2; ch++) {
        int cc = c0 + ch * TCo;

        u64 acc[8];
        #pragma unroll
        for (int i = 0; i < 8; i++) acc[i] = 0ULL;

        #pragma unroll
        for (int ph = 0; ph < 4; ph++) {
            const float* w = (ph < 2) ? w1 : w2;
            const float* ps = ((ph < 2) ? psA : psB) + n_l * (LL * 8);
            int kbase = (ph & 1) * 98;

            __syncthreads();   // ws free (gather/red readers done); ps staged on first entry
            for (int i = tid; i < 98 * 16; i += 256) {
                int kk = i >> 4, cq = i & 15;
                int kg = kbase + kk;
                int ki = kg / 14, kj = kg - ki * 14;
                int idx = (pi - ki + 13) * 27 + (pj - kj + 13);
                *(float4*)&ws[kk * TCo + cq * 4] =
                    *(const float4*)(w + (size_t)idx * CC + cc + cq * 4);
            }
            __syncthreads();

            #pragma unroll 7
            for (int kl = kst; kl < kst + 49; kl++) {
                float4 wv = *(const float4*)&ws[kl * TCo + cl * 4];
                ulonglong2 pp = *(const ulonglong2*)&ps[(kbase + kl) * 8 + sub * 4];
                u64 b0 = pk2(wv.x, wv.x), b1 = pk2(wv.y, wv.y);
                u64 b2 = pk2(wv.z, wv.z), b3 = pk2(wv.w, wv.w);
                acc[0] = ffma2(pp.x, b0, acc[0]);  acc[1] = ffma2(pp.y, b0, acc[1]);
                acc[2] = ffma2(pp.x, b1, acc[2]);  acc[3] = ffma2(pp.y, b1, acc[3]);
                acc[4] = ffma2(pp.x, b2, acc[4]);  acc[5] = ffma2(pp.y, b2, acc[5]);
                acc[6] = ffma2(pp.x, b3, acc[6]);  acc[7] = ffma2(pp.y, b3, acc[7]);
            }
        }

        // Cross-k-half reduction through smem (reuse ws area).
        __syncthreads();   // everyone done reading ws
        u64* red = (u64*)ws;
        if (kq) {
            int base = (n_l * 32 + lane) * 8;
            #pragma unroll
            for (int j = 0; j < 8; j++) red[base + j] = acc[j];
        }
        __syncthreads();

        if (kq == 0) {
            int base = (n_l * 32 + lane) * 8;
            #pragma unroll
            for (int j = 0; j < 8; j++) acc[j] = fadd2(acc[j], red[base + j]);

            float a[16];
            #pragma unroll
            for (int i = 0; i < 8; i++) upk2(acc[i], a[2 * i], a[2 * i + 1]);
            #pragma unroll
            for (int tl = 0; tl < 4; tl++) {
                int tt = sub * 4 + tl;
                int tp = tl >> 1, hi = tl & 1;
                float4 o4;
                o4.x = a[(0 * 2 + tp) * 2 + hi];
                o4.y = a[(1 * 2 + tp) * 2 + hi];
                o4.z = a[(2 * 2 + tp) * 2 + hi];
                o4.w = a[(3 * 2 + tp) * 2 + hi];
                *(float4*)(out + ((size_t)(n_l * TDIM + tt) * LP1 + qq + 1) * CC
                           + cc + cl * 4) = o4;
            }
        }
    }
}

// ---------------------------------------------------------------------------
extern "C" void kernel_launch(void* const* d_in, const int* in_sizes, int n_in,
                              void* d_out, int out_size) {
    const float* q  = (const float*)d_in[0];
    const float* k  = (const float*)d_in[1];
    const float* w1 = (const float*)d_in[2];
    const float* w2 = (const float*)d_in[3];
    float* out = (float*)d_out;

    cudaFuncSetAttribute(attn_kernel, cudaFuncAttributeMaxDynamicSharedMemorySize, A_SMEM_BYTES);
    cudaFuncSetAttribute(out_kernel,  cudaFuncAttributeMaxDynamicSharedMemorySize, O_SMEM_BYTES);

    zero_kernel<<<512, 256>>>(out);
    attn_kernel<<<dim3(HH, NT, 6), 256, A_SMEM_BYTES>>>(q, k);
    out_kernel<<<dim3(CC / (2 * TCo), LL, 1), 256, O_SMEM_BYTES>>>(w1, w2, out);
}

// round 13
// speedup vs baseline: 1.2398x; 1.0293x over previous
#include <cuda_runtime.h>
#include <math.h>
#include <stdint.h>

#define NB 4
#define TDIM 8
#define LP1 197
#define HH 12
#define DD 64
#define CC 768
#define LL 196
#define NT 28   // NB*(TDIM-1)

typedef unsigned long long u64;

__device__ __forceinline__ u64 pk2(float lo, float hi) {
    u64 r; asm("mov.b64 %0,{%1,%2};" : "=l"(r) : "f"(lo), "f"(hi)); return r;
}
__device__ __forceinline__ void upk2(u64 v, float& lo, float& hi) {
    asm("mov.b64 {%0,%1},%2;" : "=f"(lo), "=f"(hi) : "l"(v));
}
__device__ __forceinline__ u64 ffma2(u64 a, u64 b, u64 c) {
    u64 d; asm("fma.rn.f32x2 %0,%1,%2,%3;" : "=l"(d) : "l"(a), "l"(b), "l"(c)); return d;
}
__device__ __forceinline__ u64 fadd2(u64 a, u64 b) {
    u64 d; asm("add.rn.f32x2 %0,%1,%2;" : "=l"(d) : "l"(a), "l"(b)); return d;
}
__device__ __forceinline__ void red4(float* p, float a, float b, float c, float d) {
    asm volatile("red.global.add.v4.f32 [%0], {%1,%2,%3,%4};"
                 :: "l"(p), "f"(a), "f"(b), "f"(c), "f"(d) : "memory");
}
__device__ __forceinline__ void cpa16(uint32_t s, const void* g) {
    asm volatile("cp.async.cg.shared.global [%0], [%1], 16;" :: "r"(s), "l"(g) : "memory");
}
#define CPA_COMMIT() asm volatile("cp.async.commit_group;" ::: "memory")
#define CPA_WAIT(n)  asm volatile("cp.async.wait_group %0;" :: "n"(n) : "memory")

// Scratch: head-averaged attention probabilities for each half (16B aligned
// so zero_kernel can float4-store them).
__device__ __align__(16) float g_P1[NT * LL * LL];
__device__ __align__(16) float g_P2[NT * LL * LL];

// ---------------------------------------------------------------------------
// Kernel 0: zero P scratch and the cls (q=0) rows of out — float4 vectorized.
// ---------------------------------------------------------------------------
__global__ void zero_kernel(float* __restrict__ out) {
    size_t stride = (size_t)gridDim.x * blockDim.x;
    size_t i = (size_t)blockIdx.x * blockDim.x + threadIdx.x;
    float4 z = make_float4(0.f, 0.f, 0.f, 0.f);
    float4* p1 = (float4*)g_P1;
    float4* p2 = (float4*)g_P2;
    const size_t np4 = (size_t)NT * LL * LL / 4;
    for (size_t j = i; j < np4; j += stride) { p1[j] = z; p2[j] = z; }
    const size_t nc4 = (size_t)NB * TDIM * (CC / 4);
    float4* o4 = (float4*)out;
    for (size_t j = i; j < nc4; j += stride) {
        size_t nt = j / (CC / 4), c = j - nt * (CC / 4);
        o4[nt * ((size_t)LP1 * CC / 4) + c] = z;
    }
}

// ---------------------------------------------------------------------------
// Kernel 1: attention — EXACT ROUND-10 VERSION (protected best).
// ---------------------------------------------------------------------------
#define KS_STRIDE 210
#define QS_STRIDE 69
#define A_SMEM_BYTES ((64*KS_STRIDE + 64*QS_STRIDE) * 4)   // 71424 B

__device__ __forceinline__ void store_row_v4(float* Pr, const u64* pv, int tx) {
    #pragma unroll
    for (int b = 0; b < 7; b++) {
        u64 nb = __shfl_down_sync(0xffffffffu, pv[b], 1);
        if ((tx & 1) == 0 && (b < 6 || tx == 0)) {
            float a0, a1, b0, b1;
            upk2(pv[b], a0, a1);
            upk2(nb,    b0, b1);
            red4(Pr + 32 * b + 2 * tx, a0, a1, b0, b1);
        }
    }
}

__global__ __launch_bounds__(256, 3)
void attn_kernel(const float* __restrict__ q, const float* __restrict__ k) {
    extern __shared__ float sm[];
    float* ks = sm;                          // [64][210]
    float* qs = ks + 64 * KS_STRIDE;         // [64][69]

    int h    = blockIdx.x;
    int nt   = blockIdx.y;
    int half = blockIdx.z / 3;
    int qh   = blockIdx.z - half * 3;
    int n = nt / 7, t = nt - n * 7;
    int tq = (half == 0) ? t + 1 : t;
    int tk = (half == 0) ? t : t + 1;
    int q0 = qh * 64;
    int nrows = (qh == 2) ? 68 : 64;

    const float* qb = q + ((size_t)(n * TDIM + tq) * LP1 + 1) * (HH * DD) + h * DD;
    const float* kb = k + ((size_t)(n * TDIM + tk) * LP1 + 1) * (HH * DD) + h * DD;
    float* P = ((half == 0) ? g_P1 : g_P2) + (size_t)nt * LL * LL;

    int tid = threadIdx.x;

    for (int i = tid; i < LL * DD; i += 256) {
        int kk = i >> 6, d = i & 63;
        ks[d * KS_STRIDE + kk] = kb[(size_t)kk * (HH * DD) + d];
    }
    for (int i = tid; i < nrows * DD; i += 256) {
        int qq = i >> 6, d = i & 63;
        qs[d * QS_STRIDE + qq] = qb[(size_t)(q0 + qq) * (HH * DD) + d] * 0.125f;
    }
    __syncthreads();

    int tx = tid & 15, ty = tid >> 4;

    u64 acc[4][7];
    #pragma unroll
    for (int a = 0; a < 4; a++)
        #pragma unroll
        for (int b = 0; b < 7; b++) acc[a][b] = 0ULL;

    #pragma unroll 4
    for (int d = 0; d < 64; d++) {
        u64 ad[4], bv[7];
        #pragma unroll
        for (int a = 0; a < 4; a++) {
            float av = qs[d * QS_STRIDE + ty + 16 * a];
            ad[a] = pk2(av, av);
        }
        #pragma unroll
        for (int b = 0; b < 7; b++)
            bv[b] = *(const u64*)&ks[d * KS_STRIDE + 2 * tx + 32 * b];
        #pragma unroll
        for (int a = 0; a < 4; a++)
            #pragma unroll
            for (int b = 0; b < 7; b++)
                acc[a][b] = ffma2(ad[a], bv[b], acc[a][b]);
    }

    #pragma unroll
    for (int a = 0; a < 4; a++) {
        float e[14];
        #pragma unroll
        for (int b = 0; b < 7; b++) upk2(acc[a][b], e[2 * b], e[2 * b + 1]);

        bool v6 = (tx < 2);
        float mx = -1e30f;
        #pragma unroll
        for (int b = 0; b < 6; b++) mx = fmaxf(mx, fmaxf(e[2 * b], e[2 * b + 1]));
        if (v6) mx = fmaxf(mx, fmaxf(e[12], e[13]));
        #pragma unroll
        for (int off = 8; off > 0; off >>= 1)
            mx = fmaxf(mx, __shfl_xor_sync(0xffffffffu, mx, off));

        float s = 0.f;
        #pragma unroll
        for (int b = 0; b < 6; b++) {
            e[2 * b]     = __expf(e[2 * b] - mx);
            e[2 * b + 1] = __expf(e[2 * b + 1] - mx);
            s += e[2 * b] + e[2 * b + 1];
        }
        if (v6) {
            e[12] = __expf(e[12] - mx);
            e[13] = __expf(e[13] - mx);
            s += e[12] + e[13];
        }
        #pragma unroll
        for (int off = 8; off > 0; off >>= 1)
            s += __shfl_xor_sync(0xffffffffu, s, off);

        float inv = (1.f / 12.f) / s;
        u64 pv[7];
        #pragma unroll
        for (int b = 0; b < 7; b++)
            pv[b] = pk2(e[2 * b] * inv, e[2 * b + 1] * inv);
        store_row_v4(P + (size_t)(q0 + ty + 16 * a) * LL, pv, tx);
    }

    if (qh == 2) {
        int qq2 = 64 + (ty & 3);
        u64 acct[7];
        #pragma unroll
        for (int b = 0; b < 7; b++) acct[b] = 0ULL;

        #pragma unroll 4
        for (int d = 0; d < 64; d++) {
            float av = qs[d * QS_STRIDE + qq2];
            u64 ad = pk2(av, av);
            #pragma unroll
            for (int b = 0; b < 7; b++)
                acct[b] = ffma2(ad, *(const u64*)&ks[d * KS_STRIDE + 2 * tx + 32 * b], acct[b]);
        }

        float e[14];
        #pragma unroll
        for (int b = 0; b < 7; b++) upk2(acct[b], e[2 * b], e[2 * b + 1]);

        bool v6 = (tx < 2);
        float mx = -1e30f;
        #pragma unroll
        for (int b = 0; b < 6; b++) mx = fmaxf(mx, fmaxf(e[2 * b], e[2 * b + 1]));
        if (v6) mx = fmaxf(mx, fmaxf(e[12], e[13]));
        #pragma unroll
        for (int off = 8; off > 0; off >>= 1)
            mx = fmaxf(mx, __shfl_xor_sync(0xffffffffu, mx, off));

        float s = 0.f;
        #pragma unroll
        for (int b = 0; b < 6; b++) {
            e[2 * b]     = __expf(e[2 * b] - mx);
            e[2 * b + 1] = __expf(e[2 * b + 1] - mx);
            s += e[2 * b] + e[2 * b + 1];
        }
        if (v6) {
            e[12] = __expf(e[12] - mx);
            e[13] = __expf(e[13] - mx);
            s += e[12] + e[13];
        }
        #pragma unroll
        for (int off = 8; off > 0; off >>= 1)
            s += __shfl_xor_sync(0xffffffffu, s, off);

        float inv = (1.f / 12.f) / s;
        u64 pv[7];
        #pragma unroll
        for (int b = 0; b < 7; b++)
            pv[b] = pk2(e[2 * b] * inv, e[2 * b + 1] * inv);
        #pragma unroll
        for (int b = 0; b < 7; b++) {
            u64 nb = __shfl_down_sync(0xffffffffu, pv[b], 1);
            if (ty < 4 && (tx & 1) == 0 && (b < 6 || tx == 0)) {
                float a0, a1, b0, b1;
                upk2(pv[b], a0, a1);
                upk2(nb,    b0, b1);
                red4(P + (size_t)(192 + ty) * LL + 32 * b + 2 * tx, a0, a1, b0, b1);
            }
        }
    }
}

// ---------------------------------------------------------------------------
// Kernel 2: fused halves, np-merged, c-tile-paired, NOW cp.async DOUBLE-BUFFERED.
// Block = (c-pair of 128, q).  256 threads, 2 CTAs/SM (108.5KB smem).
// 8 flattened phases (2 sub-tiles x 4 gather phases); gather for phase pp+1 is
// issued via cp.async.cg into the other ws buffer BEFORE computing phase pp ->
// gather LDG latency fully hidden behind the FFMA2 loop.  Dedicated 8KB red
// area (no ws reuse).  Barrier count per phase unchanged (2).
// ---------------------------------------------------------------------------
#define TCo 64
#define WSF (98 * TCo)                  // 6272 floats per ws buffer
#define PSF (4 * LL * 8)                // 6272 floats per half
#define RED_U64 (4 * 32 * 8)            // 1024 u64 = 8192 B
#define O_SMEM_BYTES ((2*WSF + 2*PSF) * 4 + RED_U64 * 8)   // 108544 B

__global__ __launch_bounds__(256, 2)
void out_kernel(const float* __restrict__ w1, const float* __restrict__ w2,
                float* __restrict__ out) {
    extern __shared__ float sm[];
    float* psA = sm + 2 * WSF;          // [4][196*8]  slot tt = P1[t=tt-1], slot0=0
    float* psB = psA + PSF;             // [4][196*8]  slot tt = P2[tt],    slot7=0
    u64*   red = (u64*)(sm + 2 * WSF + 2 * PSF);

    int qq = blockIdx.y;
    int c0 = blockIdx.x * (2 * TCo);
    int tid = threadIdx.x;
    int pi = qq / 14, pj = qq - pi * 14;

    uint32_t ws_s0 = (uint32_t)__cvta_generic_to_shared(sm);

    // Stage P rows t-strided for all 4 n, both halves (once per block).
    #pragma unroll
    for (int r = 0; r < 28; r++) {
        int n_l = r / 7, t = r - n_l * 7;
        if (tid < LL) {
            size_t base = ((size_t)(n_l * 7 + t) * LL + qq) * LL + tid;
            psA[n_l * (LL * 8) + tid * 8 + t + 1] = g_P1[base];
            psB[n_l * (LL * 8) + tid * 8 + t]     = g_P2[base];
        }
    }
    if (tid < LL) {
        #pragma unroll
        for (int n_l = 0; n_l < 4; n_l++) {
            psA[n_l * (LL * 8) + tid * 8] = 0.f;
            psB[n_l * (LL * 8) + tid * 8 + 7] = 0.f;
        }
    }

    int wid = tid >> 5, lane = tid & 31;
    int n_l = wid >> 1, kq = wid & 1;
    int sub = lane >> 4, cl = lane & 15;
    int kst = kq * 49;

    // Issue the gather for flattened phase pp into ws[pp&1] via cp.async.
    auto gather = [&](int pp) {
        int ch = pp >> 2, ph = pp & 3;
        const float* w = (ph < 2) ? w1 : w2;
        int kbase = (ph & 1) * 98;
        int cc = c0 + ch * TCo;
        uint32_t dst = ws_s0 + (uint32_t)(pp & 1) * (WSF * 4);
        #pragma unroll
        for (int j = 0; j < 6; j++) {
            int i = tid + j * 256;
            int kk = i >> 4, cq = i & 15;
            int kg = kbase + kk;
            int ki = kg / 14, kj = kg - ki * 14;
            int idx = (pi - ki + 13) * 27 + (pj - kj + 13);
            cpa16(dst + (uint32_t)(kk * TCo + cq * 4) * 4,
                  w + (size_t)idx * CC + cc + cq * 4);
        }
        if (tid < 32) {
            int i = 1536 + tid;
            int kk = i >> 4, cq = i & 15;
            int kg = kbase + kk;
            int ki = kg / 14, kj = kg - ki * 14;
            int idx = (pi - ki + 13) * 27 + (pj - kj + 13);
            cpa16(dst + (uint32_t)(kk * TCo + cq * 4) * 4,
                  w + (size_t)idx * CC + cc + cq * 4);
        }
        CPA_COMMIT();
    };

    u64 acc[8];
    #pragma unroll
    for (int i = 0; i < 8; i++) acc[i] = 0ULL;

    gather(0);
    for (int pp = 0; pp < 8; pp++) {
        if (pp < 7) { gather(pp + 1); CPA_WAIT(1); }
        else        { CPA_WAIT(0); }
        __syncthreads();   // phase-pp data visible everywhere (also ps, iter 0)

        int ph = pp & 3, ch = pp >> 2;
        const float* ps = ((ph < 2) ? psA : psB) + n_l * (LL * 8);
        int kbase = (ph & 1) * 98;
        const float* ws = sm + (pp & 1) * WSF;

        #pragma unroll 7
        for (int kl = kst; kl < kst + 49; kl++) {
            float4 wv = *(const float4*)&ws[kl * TCo + cl * 4];
            ulonglong2 pr = *(const ulonglong2*)&ps[(kbase + kl) * 8 + sub * 4];
            u64 b0 = pk2(wv.x, wv.x), b1 = pk2(wv.y, wv.y);
            u64 b2 = pk2(wv.z, wv.z), b3 = pk2(wv.w, wv.w);
            acc[0] = ffma2(pr.x, b0, acc[0]);  acc[1] = ffma2(pr.y, b0, acc[1]);
            acc[2] = ffma2(pr.x, b1, acc[2]);  acc[3] = ffma2(pr.y, b1, acc[3]);
            acc[4] = ffma2(pr.x, b2, acc[4]);  acc[5] = ffma2(pr.y, b2, acc[5]);
            acc[6] = ffma2(pr.x, b3, acc[6]);  acc[7] = ffma2(pr.y, b3, acc[7]);
        }

        bool epi = ((pp & 3) == 3);
        if (epi && kq) {
            int base = (n_l * 32 + lane) * 8;
            #pragma unroll
            for (int j = 0; j < 8; j++) red[base + j] = acc[j];
        }
        __syncthreads();   // ws[pp&1] free for gather(pp+2); red visible if epi

        if (epi) {
            if (kq == 0) {
                int base = (n_l * 32 + lane) * 8;
                #pragma unroll
                for (int j = 0; j < 8; j++) acc[j] = fadd2(acc[j], red[base + j]);

                int cc = c0 + ch * TCo;
                float a[16];
                #pragma unroll
                for (int i = 0; i < 8; i++) upk2(acc[i], a[2 * i], a[2 * i + 1]);
                #pragma unroll
                for (int tl = 0; tl < 4; tl++) {
                    int tt = sub * 4 + tl;
                    int tp = tl >> 1, hi = tl & 1;
                    float4 o4;
                    o4.x = a[(0 * 2 + tp) * 2 + hi];
                    o4.y = a[(1 * 2 + tp) * 2 + hi];
                    o4.z = a[(2 * 2 + tp) * 2 + hi];
                    o4.w = a[(3 * 2 + tp) * 2 + hi];
                    *(float4*)(out + ((size_t)(n_l * TDIM + tt) * LP1 + qq + 1) * CC
                               + cc + cl * 4) = o4;
                }
            }
            #pragma unroll
            for (int i = 0; i < 8; i++) acc[i] = 0ULL;
        }
    }
}

// ---------------------------------------------------------------------------
extern "C" void kernel_launch(void* const* d_in, const int* in_sizes, int n_in,
                              void* d_out, int out_size) {
    const float* q  = (const float*)d_in[0];
    const float* k  = (const float*)d_in[1];
    const float* w1 = (const float*)d_in[2];
    const float* w2 = (const float*)d_in[3];
    float* out = (float*)d_out;

    cudaFuncSetAttribute(attn_kernel, cudaFuncAttributeMaxDynamicSharedMemorySize, A_SMEM_BYTES);
    cudaFuncSetAttribute(out_kernel,  cudaFuncAttributeMaxDynamicSharedMemorySize, O_SMEM_BYTES);

    zero_kernel<<<512, 256>>>(out);
    attn_kernel<<<dim3(HH, NT, 6), 256, A_SMEM_BYTES>>>(q, k);
    out_kernel<<<dim3(CC / (2 * TCo), LL, 1), 256, O_SMEM_BYTES>>>(w1, w2, out);
}